// round 4
// baseline (speedup 1.0000x reference)
#include <cuda_runtime.h>
#include <cstdint>

// ElementUpdate: out[n,:] = h_prev[n,:] + W[z[n]] @ m_curr[n,:]
// N=16384, D=128, S=119, z sorted. mma.sync m16n8k8 tf32 (compute_103-safe).
// R4: split output cols across CTAs. CTA tile = 64 rows x 64 out-cols:
// A = 64x128 (33KB), W-slice = 64x128 (33KB) -> ~67KB SMEM -> 3 CTAs/SM,
// grid=512, 24 warps/SM. Warp tile 16x32. Masked-A per sorted species segment.

static constexpr int D = 128;
static constexpr int TILE_M = 64;
static constexpr int TILE_N = 64;
static constexpr int NT = 256;
static constexpr int APAD = 132;               // conflict-free float stride
static constexpr int HDR = 1024;
static constexpr int A_BYTES = TILE_M * APAD * 4;   // 33792
static constexpr int W_BYTES = TILE_N * APAD * 4;   // 33792
static constexpr int SMEM_BYTES = HDR + A_BYTES + W_BYTES;  // 68608 -> 3 CTAs/SM

__device__ __forceinline__ uint32_t f2tf32(float f) {
    uint32_t r;
    asm("cvt.rna.tf32.f32 %0, %1;" : "=r"(r) : "f"(f));
    return r;
}

__device__ __forceinline__ void mma_tf32(float* d, const uint32_t* a,
                                         uint32_t b0, uint32_t b1) {
    asm volatile(
        "mma.sync.aligned.m16n8k8.row.col.f32.tf32.tf32.f32 "
        "{%0,%1,%2,%3}, {%4,%5,%6,%7}, {%8,%9}, {%0,%1,%2,%3};"
        : "+f"(d[0]), "+f"(d[1]), "+f"(d[2]), "+f"(d[3])
        : "r"(a[0]), "r"(a[1]), "r"(a[2]), "r"(a[3]), "r"(b0), "r"(b1));
}

__global__ void __launch_bounds__(NT, 3)
element_update_kernel(const float* __restrict__ h_prev,
                      const float* __restrict__ m_curr,
                      const int* __restrict__ atom_types,
                      const float* __restrict__ weight,
                      float* __restrict__ out) {
    extern __shared__ __align__(16) char smem[];
    const int tid = threadIdx.x;
    const int lane = tid & 31;
    const int wid = tid >> 5;
    const int R0 = (blockIdx.x >> 1) * TILE_M;   // node-row tile
    const int N0 = (blockIdx.x & 1) * TILE_N;    // out-col half

    int* sCnt  = (int*)(smem + 0);
    int* sOff  = (int*)(smem + 16);
    int* sNseg = (int*)(smem + 32);
    int* sRow  = (int*)(smem + 64);     // up to TILE_M+1 entries
    int* sSpec = (int*)(smem + 384);    // up to TILE_M entries
    uint32_t* sA = (uint32_t*)(smem + HDR);
    uint32_t* sW = (uint32_t*)(smem + HDR + A_BYTES);

    // ---- species-segment scan over TILE_M sorted z values (warps 0-1) ----
    bool bd = false; int wpre = 0, zr = 0;
    if (tid < TILE_M) {
        zr = atom_types[R0 + tid];
        int zp = (tid == 0) ? -1 : atom_types[R0 + tid - 1];
        bd = (zp != zr);
        unsigned msk = __ballot_sync(0xffffffffu, bd);
        wpre = __popc(msk & ((1u << lane) - 1u));
        if (lane == 0) sCnt[wid] = __popc(msk);
    }

    // ---- A tile fill (m_curr -> tf32 in SMEM), overlapped with scan ----
    for (int i = tid; i < TILE_M * (D / 4); i += NT) {
        int r = i >> 5, c4 = (i & 31) << 2;
        float4 v = *(const float4*)(m_curr + (size_t)(R0 + r) * D + c4);
        uint4 u;
        u.x = f2tf32(v.x); u.y = f2tf32(v.y); u.z = f2tf32(v.z); u.w = f2tf32(v.w);
        *(uint4*)(sA + r * APAD + c4) = u;
    }
    __syncthreads();
    if (tid == 0) {
        int c0 = sCnt[0], c1 = sCnt[1];
        sOff[0] = 0; sOff[1] = c0;
        *sNseg = c0 + c1;
        sRow[c0 + c1] = TILE_M;
    }
    __syncthreads();
    if (tid < TILE_M && bd) {
        int i = sOff[wid] + wpre;
        sRow[i] = tid;
        sSpec[i] = zr;
    }
    __syncthreads();
    const int nseg = *sNseg;

    // ---- warp geometry: rows [16*wr,+16) x CTA-cols [32*wc,+32) ----
    const int wr = wid >> 1;     // 0..3
    const int wc = wid & 1;      // 0..1
    const int rlo = wr * 16;
    const int lr = lane >> 2;    // 0..7
    const int lc = lane & 3;     // 0..3

    float acc[4][4];
    #pragma unroll
    for (int nt = 0; nt < 4; nt++)
        #pragma unroll
        for (int j = 0; j < 4; j++) acc[nt][j] = 0.f;

    const uint32_t* pAbase = sA + (rlo + lr) * APAD + lc;
    const uint32_t* pBbase = sW + (wc * 32 + lr) * APAD + lc;

    for (int seg = 0; seg < nseg; seg++) {
        const int a = sRow[seg];
        const int b = sRow[seg + 1];
        const int s = sSpec[seg];

        __syncthreads();   // previous segment's compute done before W overwrite
        // W[s] rows [N0, N0+64), all 128 k  (row n of sW = out-dim N0+n)
        const float* wsrc = weight + (size_t)s * (D * D) + (size_t)N0 * D;
        for (int i = tid; i < TILE_N * (D / 4); i += NT) {
            int r = i >> 5, c4 = (i & 31) << 2;
            float4 v = *(const float4*)(wsrc + (size_t)r * D + c4);
            uint4 u;
            u.x = f2tf32(v.x); u.y = f2tf32(v.y); u.z = f2tf32(v.z); u.w = f2tf32(v.w);
            *(uint4*)(sW + r * APAD + c4) = u;
        }
        __syncthreads();

        if (b > rlo && a < rlo + 16) {
            const int r0 = rlo + lr;
            const uint32_t am0 = (r0 >= a && r0 < b) ? 0xffffffffu : 0u;
            const uint32_t am1 = (r0 + 8 >= a && r0 + 8 < b) ? 0xffffffffu : 0u;

            #pragma unroll 4
            for (int ks = 0; ks < 16; ks++) {
                const int k0 = ks * 8;
                uint32_t aF[4];
                const uint32_t* pA = pAbase + k0;
                aF[0] = pA[0] & am0;
                aF[2] = pA[4] & am0;
                aF[1] = pA[8 * APAD] & am1;
                aF[3] = pA[8 * APAD + 4] & am1;
                #pragma unroll
                for (int nt = 0; nt < 4; nt++) {
                    const uint32_t* pB = pBbase + nt * (8 * APAD) + k0;
                    mma_tf32(acc[nt], aF, pB[0], pB[4]);
                }
            }
        }
    }

    // ---- epilogue: acc + h_prev -> out (coalesced float2, 32B sectors) ----
    #pragma unroll
    for (int h = 0; h < 2; h++) {
        const int r = R0 + rlo + 8 * h + lr;
        const float* hp = h_prev + (size_t)r * D;
        float* op = out + (size_t)r * D;
        #pragma unroll
        for (int nt = 0; nt < 4; nt++) {
            const int c = N0 + wc * 32 + 8 * nt + lc * 2;
            float2 hv = *(const float2*)(hp + c);
            float2 o;
            o.x = hv.x + acc[nt][2 * h + 0];
            o.y = hv.y + acc[nt][2 * h + 1];
            *(float2*)(op + c) = o;
        }
    }
}

extern "C" void kernel_launch(void* const* d_in, const int* in_sizes, int n_in,
                              void* d_out, int out_size) {
    const float* h_prev     = (const float*)d_in[0];
    const float* m_curr     = (const float*)d_in[1];
    const int*   atom_types = (const int*)d_in[2];
    const float* weight     = (const float*)d_in[3];
    float* out = (float*)d_out;

    int n_nodes = in_sizes[0] / D;       // 16384
    int grid = (n_nodes / TILE_M) * 2;   // 512

    cudaFuncSetAttribute(element_update_kernel,
                         cudaFuncAttributeMaxDynamicSharedMemorySize, SMEM_BYTES);
    element_update_kernel<<<grid, NT, SMEM_BYTES>>>(h_prev, m_curr, atom_types,
                                                    weight, out);
}